// round 3
// baseline (speedup 1.0000x reference)
#include <cuda_runtime.h>
#include <cuda_bf16.h>
#include <cstdint>
#include <math.h>

// Shapes (fixed for this problem)
#define BB 32
#define TT 4
#define LL 196
#define DD 512
#define HH 8
#define ROWS (BB*TT*LL)          // 25088
#define GK DD                    // 512
#define GN DD                    // 512

// Scratch (device globals -- no runtime allocation allowed)
__device__ float g_Y[(size_t)ROWS * DD];
__device__ float g_S2[(size_t)ROWS * DD];
__device__ unsigned long long g_qb[TT*BB*HH*LL];
__device__ unsigned long long g_kb[TT*BB*HH*LL];
__device__ unsigned long long g_vb[TT*BB*HH*LL];

// ---------------------------------------------------------------------------
// bf16x3-split tensor-core GEMM (fp32-accurate): C = A @ W^T + bias
// A: [ROWS,512] row-major; W: [512,512] row-major (out,in).
// a = a0+a1+a2 (bf16 splits, residual ~2^-27). Terms kept:
//   a0b0 + a0b1 + a1b0 + a1b1 + a0b2 + a2b0   (error ~2^-27 per product)
// EXACT_A: A is {0,1} spikes (exact in bf16) -> only a0{b0,b1,b2} (3 terms).
// Tile: 128x128x16, 256 threads, 8 warps x (64x32) via m16n8k16.
// SMEM: per split plane, u32-packed bf16 k-pairs at [k4blk][row][k2&3],
// pitch 528 u32 per k4 block -> conflict-free LDS and STS.64.
// ---------------------------------------------------------------------------
#define BKC 16
#define PLANE 1056   // 2 k4-blocks * 528

__device__ __forceinline__ void mma_bf16(float* c, const uint32_t* a, const uint32_t* b) {
    asm volatile(
        "mma.sync.aligned.m16n8k16.row.col.f32.bf16.bf16.f32 "
        "{%0,%1,%2,%3}, {%4,%5,%6,%7}, {%8,%9}, {%0,%1,%2,%3};\n"
        : "+f"(c[0]), "+f"(c[1]), "+f"(c[2]), "+f"(c[3])
        : "r"(a[0]), "r"(a[1]), "r"(a[2]), "r"(a[3]), "r"(b[0]), "r"(b[1]));
}

__device__ __forceinline__ uint32_t pkbf(float lo, float hi) {
    __nv_bfloat16 l = __float2bfloat16_rn(lo);
    __nv_bfloat16 h = __float2bfloat16_rn(hi);
    return (uint32_t)__bfloat16_as_ushort(l) | ((uint32_t)__bfloat16_as_ushort(h) << 16);
}

// split f into 3 bf16 parts (returns as floats for packing convenience)
__device__ __forceinline__ void split3(float f, float& s0, float& s1, float& s2) {
    __nv_bfloat16 h0 = __float2bfloat16_rn(f);
    s0 = __bfloat162float(h0);
    float r1 = f - s0;
    __nv_bfloat16 h1 = __float2bfloat16_rn(r1);
    s1 = __bfloat162float(h1);
    s2 = r1 - s1;   // will be rounded to bf16 at pack time
}

template <bool EXACT_A>
__global__ void __launch_bounds__(256) gemm_bf16x3_kernel(
    const float* __restrict__ A, const float* __restrict__ W,
    const float* __restrict__ bias, float* __restrict__ C)
{
    __shared__ uint32_t sA[(EXACT_A ? 1 : 3) * PLANE];
    __shared__ uint32_t sB[3 * PLANE];

    const int tid = threadIdx.x;
    const int bn = blockIdx.x * 128, bm = blockIdx.y * 128;
    const int w = tid >> 5, lane = tid & 31;
    const int wm = (w & 1) * 64, wn = (w >> 1) * 32;
    const int g = lane >> 2, tg = lane & 3;

    float acc[4][4][4];
#pragma unroll
    for (int mi = 0; mi < 4; mi++)
#pragma unroll
        for (int ni = 0; ni < 4; ni++)
#pragma unroll
            for (int r = 0; r < 4; r++) acc[mi][ni][r] = 0.f;

    for (int k0 = 0; k0 < GK; k0 += BKC) {
        // ---- fill smem: 128x16 of A and W, split into bf16 planes ----
#pragma unroll
        for (int rep = 0; rep < 2; rep++) {
            const int lin = rep * 256 + tid;
            const int row = lin >> 2;        // 0..127
            const int f4c = lin & 3;         // k-offset = f4c*4
            const int sidx = (f4c >> 1) * 528 + row * 4 + 2 * (f4c & 1);

            float4 a4 = *(const float4*)(A + (size_t)(bm + row) * GK + k0 + f4c * 4);
            float4 w4 = *(const float4*)(W + (size_t)(bn + row) * GK + k0 + f4c * 4);

            if (EXACT_A) {
                *(uint2*)&sA[sidx] = make_uint2(pkbf(a4.x, a4.y), pkbf(a4.z, a4.w));
            } else {
                float x0, x1, x2, y0, y1, y2, z0, z1, z2, u0, u1, u2;
                split3(a4.x, x0, x1, x2); split3(a4.y, y0, y1, y2);
                split3(a4.z, z0, z1, z2); split3(a4.w, u0, u1, u2);
                *(uint2*)&sA[0 * PLANE + sidx] = make_uint2(pkbf(x0, y0), pkbf(z0, u0));
                *(uint2*)&sA[1 * PLANE + sidx] = make_uint2(pkbf(x1, y1), pkbf(z1, u1));
                *(uint2*)&sA[2 * PLANE + sidx] = make_uint2(pkbf(x2, y2), pkbf(z2, u2));
            }
            {
                float x0, x1, x2, y0, y1, y2, z0, z1, z2, u0, u1, u2;
                split3(w4.x, x0, x1, x2); split3(w4.y, y0, y1, y2);
                split3(w4.z, z0, z1, z2); split3(w4.w, u0, u1, u2);
                *(uint2*)&sB[0 * PLANE + sidx] = make_uint2(pkbf(x0, y0), pkbf(z0, u0));
                *(uint2*)&sB[1 * PLANE + sidx] = make_uint2(pkbf(x1, y1), pkbf(z1, u1));
                *(uint2*)&sB[2 * PLANE + sidx] = make_uint2(pkbf(x2, y2), pkbf(z2, u2));
            }
        }
        __syncthreads();

        // ---- one k16 mma step ----
        uint32_t bf[3][4][2];
#pragma unroll
        for (int s = 0; s < 3; s++)
#pragma unroll
            for (int ni = 0; ni < 4; ni++) {
                const int c0 = wn + ni * 8 + g;
                bf[s][ni][0] = sB[s * PLANE + c0 * 4 + tg];
                bf[s][ni][1] = sB[s * PLANE + 528 + c0 * 4 + tg];
            }
#pragma unroll
        for (int mi = 0; mi < 4; mi++) {
            const int r0 = wm + mi * 16 + g;
            uint32_t af[EXACT_A ? 1 : 3][4];
#pragma unroll
            for (int s = 0; s < (EXACT_A ? 1 : 3); s++) {
                af[s][0] = sA[s * PLANE + r0 * 4 + tg];
                af[s][1] = sA[s * PLANE + (r0 + 8) * 4 + tg];
                af[s][2] = sA[s * PLANE + 528 + r0 * 4 + tg];
                af[s][3] = sA[s * PLANE + 528 + (r0 + 8) * 4 + tg];
            }
#pragma unroll
            for (int ni = 0; ni < 4; ni++) {
                mma_bf16(acc[mi][ni], af[0], bf[0][ni]);
                mma_bf16(acc[mi][ni], af[0], bf[1][ni]);
                mma_bf16(acc[mi][ni], af[0], bf[2][ni]);
                if (!EXACT_A) {
                    mma_bf16(acc[mi][ni], af[1], bf[0][ni]);
                    mma_bf16(acc[mi][ni], af[1], bf[1][ni]);
                    mma_bf16(acc[mi][ni], af[2], bf[0][ni]);
                }
            }
        }
        __syncthreads();
    }

#pragma unroll
    for (int mi = 0; mi < 4; mi++) {
        const int row = bm + wm + mi * 16 + g;
#pragma unroll
        for (int ni = 0; ni < 4; ni++) {
            const int col = bn + wn + ni * 8 + tg * 2;
            const float b0 = bias[col], b1 = bias[col + 1];
            *(float2*)(C + (size_t)row * GN + col) =
                make_float2(acc[mi][ni][0] + b0, acc[mi][ni][1] + b1);
            *(float2*)(C + (size_t)(row + 8) * GN + col) =
                make_float2(acc[mi][ni][2] + b0, acc[mi][ni][3] + b1);
        }
    }
}

// ---------------------------------------------------------------------------
// Fused LayerNorm + LIF scan over T + spike emission (unchanged from R1).
// ---------------------------------------------------------------------------
__global__ void __launch_bounds__(256) ln_lif_kernel(
    const float* __restrict__ Y, const float* __restrict__ g,
    const float* __restrict__ be, float thr,
    unsigned long long* __restrict__ bits, float* __restrict__ outf)
{
    const int bl = blockIdx.x;
    const int b = bl / LL, l = bl % LL;
    const int tid = threadIdx.x, w = tid >> 5, lane = tid & 31;
    const int cA = w * 64 + lane, cB = cA + 32;
    __shared__ float red[8];
    const float gA = g[cA], gB = g[cB], beA = be[cA], beB = be[cB];
    float vA = 0.f, vB = 0.f;

    for (int t = 0; t < TT; t++) {
        const size_t roff = ((size_t)((b * TT + t) * LL + l)) * DD;
        const float yA = Y[roff + cA], yB = Y[roff + cB];

        float s = yA + yB;
#pragma unroll
        for (int o = 16; o; o >>= 1) s += __shfl_xor_sync(0xffffffffu, s, o);
        if (lane == 0) red[w] = s;
        __syncthreads();
        float S = 0.f;
#pragma unroll
        for (int i = 0; i < 8; i++) S += red[i];
        const float mean = S * (1.f / 512.f);
        __syncthreads();

        const float dA = yA - mean, dB = yB - mean;
        float q = dA * dA + dB * dB;
#pragma unroll
        for (int o = 16; o; o >>= 1) q += __shfl_xor_sync(0xffffffffu, q, o);
        if (lane == 0) red[w] = q;
        __syncthreads();
        float Q = 0.f;
#pragma unroll
        for (int i = 0; i < 8; i++) Q += red[i];
        __syncthreads();
        const float var = Q * (1.f / 512.f);
        const float rstd = (float)(1.0 / sqrt((double)var + 1e-5));

        const float nA = dA * rstd * gA + beA;
        const float nB = dB * rstd * gB + beB;

        vA = (vA + nA) * 0.5f;
        vB = (vB + nB) * 0.5f;
        const bool sA = (vA >= thr), sB = (vB >= thr);
        if (sA) vA = 0.f;
        if (sB) vB = 0.f;

        if (bits) {
            unsigned mA = __ballot_sync(0xffffffffu, sA);
            unsigned mB = __ballot_sync(0xffffffffu, sB);
            if (lane == 0)
                bits[((size_t)(t * BB + b) * HH + w) * LL + l] =
                    (unsigned long long)mA | ((unsigned long long)mB << 32);
        } else {
            outf[roff + cA] = sA ? 1.f : 0.f;
            outf[roff + cB] = sB ? 1.f : 0.f;
        }
    }
}

// ---------------------------------------------------------------------------
// Binary attention: o[l,c] = 0.25 * sum_j popcount(q_l & k_j) * v_bit(j,c)
// ---------------------------------------------------------------------------
__global__ void __launch_bounds__(256) attn_kernel(
    const unsigned long long* __restrict__ qb,
    const unsigned long long* __restrict__ kb,
    const unsigned long long* __restrict__ vb,
    float* __restrict__ O)
{
    __shared__ unsigned long long ks[LL], vs[LL];
    const int blk = blockIdx.x;
    const int t = blk >> 8;
    const int b = (blk >> 3) & 31;
    const int h = blk & 7;
    const size_t base = ((size_t)(t * BB + b) * HH + h) * LL;
    const int tid = threadIdx.x;
    if (tid < LL) { ks[tid] = kb[base + tid]; vs[tid] = vb[base + tid]; }
    __syncthreads();

    const int w = tid >> 5, lane = tid & 31;
    for (int l0 = w * 4; l0 < LL; l0 += 32) {
        const unsigned long long q0 = qb[base + l0 + 0];
        const unsigned long long q1 = qb[base + l0 + 1];
        const unsigned long long q2 = qb[base + l0 + 2];
        const unsigned long long q3 = qb[base + l0 + 3];
        int a00 = 0, a01 = 0, a10 = 0, a11 = 0;
        int a20 = 0, a21 = 0, a30 = 0, a31 = 0;
        for (int j = 0; j < LL; j++) {
            const unsigned long long kj = ks[j];
            const unsigned long long vj = vs[j];
            const int b0 = (int)((vj >> lane) & 1ull);
            const int b1 = (int)((vj >> (lane + 32)) & 1ull);
            const int w0 = __popcll(q0 & kj);
            const int w1 = __popcll(q1 & kj);
            const int w2 = __popcll(q2 & kj);
            const int w3 = __popcll(q3 & kj);
            a00 += b0 * w0; a01 += b1 * w0;
            a10 += b0 * w1; a11 += b1 * w1;
            a20 += b0 * w2; a21 += b1 * w2;
            a30 += b0 * w3; a31 += b1 * w3;
        }
        const int cb = h * 64 + lane;
        const size_t r0 = ((size_t)((b * TT + t) * LL + l0)) * DD;
        O[r0 +        cb] = a00 * 0.25f;  O[r0 +        cb + 32] = a01 * 0.25f;
        O[r0 +  512 + cb] = a10 * 0.25f;  O[r0 +  512 + cb + 32] = a11 * 0.25f;
        O[r0 + 1024 + cb] = a20 * 0.25f;  O[r0 + 1024 + cb + 32] = a21 * 0.25f;
        O[r0 + 1536 + cb] = a30 * 0.25f;  O[r0 + 1536 + cb + 32] = a31 * 0.25f;
    }
}

// ---------------------------------------------------------------------------
// LIF (thr = 0.5) on attention output. Writes fp32 0/1 spikes.
// ---------------------------------------------------------------------------
__global__ void __launch_bounds__(256) lif_attn_kernel(
    const float* __restrict__ O, float* __restrict__ S2)
{
    const int idx = blockIdx.x * 256 + threadIdx.x;
    if (idx >= BB * LL * DD) return;
    const int c = idx & 511;
    const int bl = idx >> 9;
    const int b = bl / LL, l = bl % LL;
    float v = 0.f;
#pragma unroll
    for (int t = 0; t < TT; t++) {
        const size_t off = ((size_t)((b * TT + t) * LL + l)) * DD + c;
        const float x = O[off];
        v = (v + x) * 0.5f;
        const bool s = (v >= 0.5f);
        S2[off] = s ? 1.f : 0.f;
        if (s) v = 0.f;
    }
}

// ---------------------------------------------------------------------------
extern "C" void kernel_launch(void* const* d_in, const int* in_sizes, int n_in,
                              void* d_out, int out_size)
{
    const float* x   = (const float*)d_in[0];
    const float* Wq  = (const float*)d_in[1];
    const float* bq  = (const float*)d_in[2];
    const float* gq  = (const float*)d_in[3];
    const float* beq = (const float*)d_in[4];
    const float* Wk  = (const float*)d_in[5];
    const float* bk  = (const float*)d_in[6];
    const float* gk  = (const float*)d_in[7];
    const float* bek = (const float*)d_in[8];
    const float* Wv  = (const float*)d_in[9];
    const float* bv  = (const float*)d_in[10];
    const float* gv  = (const float*)d_in[11];
    const float* bev = (const float*)d_in[12];
    const float* Wl  = (const float*)d_in[13];
    const float* bl_ = (const float*)d_in[14];
    const float* gl  = (const float*)d_in[15];
    const float* bel = (const float*)d_in[16];
    float* out = (float*)d_out;

    float *Y, *S2;
    unsigned long long *qb, *kb, *vb;
    cudaGetSymbolAddress((void**)&Y,  g_Y);
    cudaGetSymbolAddress((void**)&S2, g_S2);
    cudaGetSymbolAddress((void**)&qb, g_qb);
    cudaGetSymbolAddress((void**)&kb, g_kb);
    cudaGetSymbolAddress((void**)&vb, g_vb);

    const dim3 ggrid(GN / 128, ROWS / 128);   // (4, 196)
    const int nBL = BB * LL;                  // 6272

    gemm_bf16x3_kernel<false><<<ggrid, 256>>>(x, Wq, bq, Y);
    ln_lif_kernel<<<nBL, 256>>>(Y, gq, beq, 1.0f, qb, nullptr);
    gemm_bf16x3_kernel<false><<<ggrid, 256>>>(x, Wk, bk, Y);
    ln_lif_kernel<<<nBL, 256>>>(Y, gk, bek, 1.0f, kb, nullptr);
    gemm_bf16x3_kernel<false><<<ggrid, 256>>>(x, Wv, bv, Y);
    ln_lif_kernel<<<nBL, 256>>>(Y, gv, bev, 1.0f, vb, nullptr);

    attn_kernel<<<TT * BB * HH, 256>>>(qb, kb, vb, Y);
    lif_attn_kernel<<<(BB * LL * DD + 255) / 256, 256>>>(Y, S2);

    gemm_bf16x3_kernel<true><<<ggrid, 256>>>(S2, Wl, bl_, Y);
    ln_lif_kernel<<<nBL, 256>>>(Y, gl, bel, 1.0f, nullptr, out);
}

// round 4
// speedup vs baseline: 1.1320x; 1.1320x over previous
#include <cuda_runtime.h>
#include <cuda_bf16.h>
#include <cstdint>
#include <math.h>

// Shapes (fixed for this problem)
#define BB 32
#define TT 4
#define LL 196
#define DD 512
#define HH 8
#define ROWS (BB*TT*LL)          // 25088
#define GK DD
#define GN DD

// Scratch (device globals)
__device__ float g_Y[(size_t)ROWS * DD];
__device__ __nv_bfloat16 g_xs[3 * (size_t)ROWS * DD];   // x split planes
__device__ __nv_bfloat16 g_ws[12 * (size_t)DD * DD];    // 4 weights x 3 planes
__device__ __nv_bfloat16 g_s2b[(size_t)ROWS * DD];      // attn-LIF spikes (bf16 exact)
__device__ unsigned long long g_qb[TT*BB*HH*LL];
__device__ unsigned long long g_kb[TT*BB*HH*LL];
__device__ unsigned long long g_vb[TT*BB*HH*LL];

// ---------------------------------------------------------------------------
__device__ __forceinline__ void mma_bf16(float* c, const uint32_t* a, const uint32_t* b) {
    asm volatile(
        "mma.sync.aligned.m16n8k16.row.col.f32.bf16.bf16.f32 "
        "{%0,%1,%2,%3}, {%4,%5,%6,%7}, {%8,%9}, {%0,%1,%2,%3};\n"
        : "+f"(c[0]), "+f"(c[1]), "+f"(c[2]), "+f"(c[3])
        : "r"(a[0]), "r"(a[1]), "r"(a[2]), "r"(a[3]), "r"(b[0]), "r"(b[1]));
}

__device__ __forceinline__ void split3(float f, float& s0, float& s1, float& s2) {
    s0 = __bfloat162float(__float2bfloat16_rn(f));
    float r1 = f - s0;
    s1 = __bfloat162float(__float2bfloat16_rn(r1));
    s2 = r1 - s1;   // rounded to bf16 at store
}

// Split fp32 array into 3 bf16 planes. n must be a multiple of 4.
__global__ void __launch_bounds__(256) split3_kernel(
    const float* __restrict__ X, __nv_bfloat16* __restrict__ P0,
    __nv_bfloat16* __restrict__ P1, __nv_bfloat16* __restrict__ P2, size_t n)
{
    const size_t idx = ((size_t)blockIdx.x * 256 + threadIdx.x) * 4;
    if (idx >= n) return;
    float4 v = *(const float4*)(X + idx);
    float a0,a1,a2,b0,b1,b2,c0,c1,c2,d0,d1,d2;
    split3(v.x, a0,a1,a2); split3(v.y, b0,b1,b2);
    split3(v.z, c0,c1,c2); split3(v.w, d0,d1,d2);
    __nv_bfloat162 p;
    p = __nv_bfloat162(__float2bfloat16_rn(a0), __float2bfloat16_rn(b0));
    *(__nv_bfloat162*)(P0 + idx) = p;
    p = __nv_bfloat162(__float2bfloat16_rn(c0), __float2bfloat16_rn(d0));
    *(__nv_bfloat162*)(P0 + idx + 2) = p;
    p = __nv_bfloat162(__float2bfloat16_rn(a1), __float2bfloat16_rn(b1));
    *(__nv_bfloat162*)(P1 + idx) = p;
    p = __nv_bfloat162(__float2bfloat16_rn(c1), __float2bfloat16_rn(d1));
    *(__nv_bfloat162*)(P1 + idx + 2) = p;
    p = __nv_bfloat162(__float2bfloat16_rn(a2), __float2bfloat16_rn(b2));
    *(__nv_bfloat162*)(P2 + idx) = p;
    p = __nv_bfloat162(__float2bfloat16_rn(c2), __float2bfloat16_rn(d2));
    *(__nv_bfloat162*)(P2 + idx + 2) = p;
}

// ---------------------------------------------------------------------------
// bf16x3 GEMM on pre-split planes: C = A @ W^T + bias.
// A planes: bf16 [ROWS,512] (x3, stride ROWS*DD), B planes: bf16 [512,512] (x3).
// EXACT_A: A is exact bf16 (spikes) -> single A plane, 3 terms.
// Tile 128x128x16, 256 thr, 8 warps x (64x32) m16n8k16; cp.async 2-stage.
// SMEM u32 layout per plane: [k8blk(2)*512 + row*4 + kpair] -- all fragment
// LDS are 32 consecutive words -> conflict-free without padding.
// ---------------------------------------------------------------------------
#define PLANE 1024

template <bool EXACT_A>
__global__ void __launch_bounds__(256) gemm_pre_kernel(
    const __nv_bfloat16* __restrict__ Ap, const __nv_bfloat16* __restrict__ Bp,
    const float* __restrict__ bias, float* __restrict__ C)
{
    constexpr int APL = EXACT_A ? 1 : 3;
    __shared__ uint32_t sA[2][APL * PLANE];
    __shared__ uint32_t sB[2][3 * PLANE];

    const int tid = threadIdx.x;
    const int bn = blockIdx.x * 128, bm = blockIdx.y * 128;
    const int w = tid >> 5, lane = tid & 31;
    const int wm = (w & 1) * 64, wn = (w >> 1) * 32;
    const int g = lane >> 2, tg = lane & 3;

    const int lrow = tid >> 1;          // 0..127
    const int kh = tid & 1;             // k8-half

    float acc[4][4][4];
#pragma unroll
    for (int mi = 0; mi < 4; mi++)
#pragma unroll
        for (int ni = 0; ni < 4; ni++)
#pragma unroll
            for (int r = 0; r < 4; r++) acc[mi][ni][r] = 0.f;

    uint32_t sAa = (uint32_t)__cvta_generic_to_shared(&sA[0][0]);
    uint32_t sBa = (uint32_t)__cvta_generic_to_shared(&sB[0][0]);
    const int dstoff = (kh * 512 + lrow * 4) * 4;

    auto stage_load = [&](int buf, int k0) {
        const uint32_t aBase = sAa + buf * (APL * PLANE * 4) + dstoff;
        const uint32_t bBase = sBa + buf * (3 * PLANE * 4) + dstoff;
#pragma unroll
        for (int p = 0; p < APL; p++) {
            const __nv_bfloat16* src = Ap + (size_t)p * ((size_t)ROWS * DD)
                                          + (size_t)(bm + lrow) * GK + k0 + kh * 8;
            asm volatile("cp.async.cg.shared.global [%0], [%1], 16;\n"
                         :: "r"(aBase + p * PLANE * 4), "l"(src));
        }
#pragma unroll
        for (int p = 0; p < 3; p++) {
            const __nv_bfloat16* src = Bp + (size_t)p * ((size_t)DD * DD)
                                          + (size_t)(bn + lrow) * GK + k0 + kh * 8;
            asm volatile("cp.async.cg.shared.global [%0], [%1], 16;\n"
                         :: "r"(bBase + p * PLANE * 4), "l"(src));
        }
        asm volatile("cp.async.commit_group;\n");
    };

    stage_load(0, 0);

    for (int s = 0; s < GK / 16; s++) {
        const int cur = s & 1;
        if (s + 1 < GK / 16) {
            stage_load(cur ^ 1, (s + 1) * 16);
            asm volatile("cp.async.wait_group 1;\n");
        } else {
            asm volatile("cp.async.wait_group 0;\n");
        }
        __syncthreads();

        uint32_t bf[3][4][2];
#pragma unroll
        for (int p = 0; p < 3; p++)
#pragma unroll
            for (int ni = 0; ni < 4; ni++) {
                const int c0 = wn + ni * 8 + g;
                bf[p][ni][0] = sB[cur][p * PLANE + c0 * 4 + tg];
                bf[p][ni][1] = sB[cur][p * PLANE + 512 + c0 * 4 + tg];
            }
#pragma unroll
        for (int mi = 0; mi < 4; mi++) {
            const int r0 = wm + mi * 16 + g;
            uint32_t af[APL][4];
#pragma unroll
            for (int p = 0; p < APL; p++) {
                af[p][0] = sA[cur][p * PLANE + r0 * 4 + tg];
                af[p][1] = sA[cur][p * PLANE + (r0 + 8) * 4 + tg];
                af[p][2] = sA[cur][p * PLANE + 512 + r0 * 4 + tg];
                af[p][3] = sA[cur][p * PLANE + 512 + (r0 + 8) * 4 + tg];
            }
#pragma unroll
            for (int ni = 0; ni < 4; ni++) {
                mma_bf16(acc[mi][ni], af[0], bf[0][ni]);
                mma_bf16(acc[mi][ni], af[0], bf[1][ni]);
                mma_bf16(acc[mi][ni], af[0], bf[2][ni]);
                if (!EXACT_A) {
                    mma_bf16(acc[mi][ni], af[1], bf[0][ni]);
                    mma_bf16(acc[mi][ni], af[1], bf[1][ni]);
                    mma_bf16(acc[mi][ni], af[2], bf[0][ni]);
                }
            }
        }
        __syncthreads();
    }

#pragma unroll
    for (int mi = 0; mi < 4; mi++) {
        const int row = bm + wm + mi * 16 + g;
#pragma unroll
        for (int ni = 0; ni < 4; ni++) {
            const int col = bn + wn + ni * 8 + tg * 2;
            const float b0 = bias[col], b1 = bias[col + 1];
            *(float2*)(C + (size_t)row * GN + col) =
                make_float2(acc[mi][ni][0] + b0, acc[mi][ni][1] + b1);
            *(float2*)(C + (size_t)(row + 8) * GN + col) =
                make_float2(acc[mi][ni][2] + b0, acc[mi][ni][3] + b1);
        }
    }
}

// ---------------------------------------------------------------------------
// Fused LayerNorm + LIF scan over T + spike emission.
// ---------------------------------------------------------------------------
__global__ void __launch_bounds__(256) ln_lif_kernel(
    const float* __restrict__ Y, const float* __restrict__ g,
    const float* __restrict__ be, float thr,
    unsigned long long* __restrict__ bits, float* __restrict__ outf)
{
    const int bl = blockIdx.x;
    const int b = bl / LL, l = bl % LL;
    const int tid = threadIdx.x, w = tid >> 5, lane = tid & 31;
    const int cA = w * 64 + lane, cB = cA + 32;
    __shared__ float red[8];
    const float gA = g[cA], gB = g[cB], beA = be[cA], beB = be[cB];
    float vA = 0.f, vB = 0.f;

    for (int t = 0; t < TT; t++) {
        const size_t roff = ((size_t)((b * TT + t) * LL + l)) * DD;
        const float yA = Y[roff + cA], yB = Y[roff + cB];

        float s = yA + yB;
#pragma unroll
        for (int o = 16; o; o >>= 1) s += __shfl_xor_sync(0xffffffffu, s, o);
        if (lane == 0) red[w] = s;
        __syncthreads();
        float S = 0.f;
#pragma unroll
        for (int i = 0; i < 8; i++) S += red[i];
        const float mean = S * (1.f / 512.f);
        __syncthreads();

        const float dA = yA - mean, dB = yB - mean;
        float q = dA * dA + dB * dB;
#pragma unroll
        for (int o = 16; o; o >>= 1) q += __shfl_xor_sync(0xffffffffu, q, o);
        if (lane == 0) red[w] = q;
        __syncthreads();
        float Q = 0.f;
#pragma unroll
        for (int i = 0; i < 8; i++) Q += red[i];
        __syncthreads();
        const float var = Q * (1.f / 512.f);
        const float rstd = (float)(1.0 / sqrt((double)var + 1e-5));

        const float nA = dA * rstd * gA + beA;
        const float nB = dB * rstd * gB + beB;

        vA = (vA + nA) * 0.5f;
        vB = (vB + nB) * 0.5f;
        const bool sA = (vA >= thr), sB = (vB >= thr);
        if (sA) vA = 0.f;
        if (sB) vB = 0.f;

        if (bits) {
            unsigned mA = __ballot_sync(0xffffffffu, sA);
            unsigned mB = __ballot_sync(0xffffffffu, sB);
            if (lane == 0)
                bits[((size_t)(t * BB + b) * HH + w) * LL + l] =
                    (unsigned long long)mA | ((unsigned long long)mB << 32);
        } else {
            outf[roff + cA] = sA ? 1.f : 0.f;
            outf[roff + cB] = sB ? 1.f : 0.f;
        }
    }
}

// ---------------------------------------------------------------------------
// Binary attention: o[l,c] = 0.25 * sum_j popcount(q_l & k_j) * v_bit(j,c)
// ---------------------------------------------------------------------------
__global__ void __launch_bounds__(256) attn_kernel(
    const unsigned long long* __restrict__ qb,
    const unsigned long long* __restrict__ kb,
    const unsigned long long* __restrict__ vb,
    float* __restrict__ O)
{
    __shared__ unsigned long long ks[LL], vs[LL];
    const int blk = blockIdx.x;
    const int t = blk >> 8;
    const int b = (blk >> 3) & 31;
    const int h = blk & 7;
    const size_t base = ((size_t)(t * BB + b) * HH + h) * LL;
    const int tid = threadIdx.x;
    if (tid < LL) { ks[tid] = kb[base + tid]; vs[tid] = vb[base + tid]; }
    __syncthreads();

    const int w = tid >> 5, lane = tid & 31;
    for (int l0 = w * 4; l0 < LL; l0 += 32) {
        const unsigned long long q0 = qb[base + l0 + 0];
        const unsigned long long q1 = qb[base + l0 + 1];
        const unsigned long long q2 = qb[base + l0 + 2];
        const unsigned long long q3 = qb[base + l0 + 3];
        int a00 = 0, a01 = 0, a10 = 0, a11 = 0;
        int a20 = 0, a21 = 0, a30 = 0, a31 = 0;
        for (int j = 0; j < LL; j++) {
            const unsigned long long kj = ks[j];
            const unsigned long long vj = vs[j];
            const int b0 = (int)((vj >> lane) & 1ull);
            const int b1 = (int)((vj >> (lane + 32)) & 1ull);
            const int w0 = __popcll(q0 & kj);
            const int w1 = __popcll(q1 & kj);
            const int w2 = __popcll(q2 & kj);
            const int w3 = __popcll(q3 & kj);
            a00 += b0 * w0; a01 += b1 * w0;
            a10 += b0 * w1; a11 += b1 * w1;
            a20 += b0 * w2; a21 += b1 * w2;
            a30 += b0 * w3; a31 += b1 * w3;
        }
        const int cb = h * 64 + lane;
        const size_t r0 = ((size_t)((b * TT + t) * LL + l0)) * DD;
        O[r0 +        cb] = a00 * 0.25f;  O[r0 +        cb + 32] = a01 * 0.25f;
        O[r0 +  512 + cb] = a10 * 0.25f;  O[r0 +  512 + cb + 32] = a11 * 0.25f;
        O[r0 + 1024 + cb] = a20 * 0.25f;  O[r0 + 1024 + cb + 32] = a21 * 0.25f;
        O[r0 + 1536 + cb] = a30 * 0.25f;  O[r0 + 1536 + cb + 32] = a31 * 0.25f;
    }
}

// ---------------------------------------------------------------------------
// LIF (thr = 0.5) on attention output. Writes bf16 0/1 spikes (exact).
// ---------------------------------------------------------------------------
__global__ void __launch_bounds__(256) lif_attn_kernel(
    const float* __restrict__ O, __nv_bfloat16* __restrict__ S2)
{
    const int idx = blockIdx.x * 256 + threadIdx.x;
    if (idx >= BB * LL * DD) return;
    const int c = idx & 511;
    const int bl = idx >> 9;
    const int b = bl / LL, l = bl % LL;
    float v = 0.f;
#pragma unroll
    for (int t = 0; t < TT; t++) {
        const size_t off = ((size_t)((b * TT + t) * LL + l)) * DD + c;
        const float x = O[off];
        v = (v + x) * 0.5f;
        const bool s = (v >= 0.5f);
        S2[off] = s ? __float2bfloat16(1.f) : __float2bfloat16(0.f);
        if (s) v = 0.f;
    }
}

// ---------------------------------------------------------------------------
extern "C" void kernel_launch(void* const* d_in, const int* in_sizes, int n_in,
                              void* d_out, int out_size)
{
    const float* x   = (const float*)d_in[0];
    const float* Wq  = (const float*)d_in[1];
    const float* bq  = (const float*)d_in[2];
    const float* gq  = (const float*)d_in[3];
    const float* beq = (const float*)d_in[4];
    const float* Wk  = (const float*)d_in[5];
    const float* bk  = (const float*)d_in[6];
    const float* gk  = (const float*)d_in[7];
    const float* bek = (const float*)d_in[8];
    const float* Wv  = (const float*)d_in[9];
    const float* bv  = (const float*)d_in[10];
    const float* gv  = (const float*)d_in[11];
    const float* bev = (const float*)d_in[12];
    const float* Wl  = (const float*)d_in[13];
    const float* bl_ = (const float*)d_in[14];
    const float* gl  = (const float*)d_in[15];
    const float* bel = (const float*)d_in[16];
    float* out = (float*)d_out;

    float* Y;
    __nv_bfloat16 *xs, *ws, *s2b;
    unsigned long long *qb, *kb, *vb;
    cudaGetSymbolAddress((void**)&Y,   g_Y);
    cudaGetSymbolAddress((void**)&xs,  g_xs);
    cudaGetSymbolAddress((void**)&ws,  g_ws);
    cudaGetSymbolAddress((void**)&s2b, g_s2b);
    cudaGetSymbolAddress((void**)&qb,  g_qb);
    cudaGetSymbolAddress((void**)&kb,  g_kb);
    cudaGetSymbolAddress((void**)&vb,  g_vb);

    const size_t nX = (size_t)ROWS * DD;      // 12,845,056
    const size_t nW = (size_t)DD * DD;        // 262,144

    // Pre-split x and all weights into bf16 planes
    split3_kernel<<<(unsigned)(nX / 1024), 256>>>(x,  xs, xs + nX, xs + 2 * nX, nX);
    split3_kernel<<<(unsigned)(nW / 1024), 256>>>(Wq, ws + 0*nW, ws + 1*nW, ws + 2*nW, nW);
    split3_kernel<<<(unsigned)(nW / 1024), 256>>>(Wk, ws + 3*nW, ws + 4*nW, ws + 5*nW, nW);
    split3_kernel<<<(unsigned)(nW / 1024), 256>>>(Wv, ws + 6*nW, ws + 7*nW, ws + 8*nW, nW);
    split3_kernel<<<(unsigned)(nW / 1024), 256>>>(Wl, ws + 9*nW, ws + 10*nW, ws + 11*nW, nW);

    const dim3 ggrid(GN / 128, ROWS / 128);   // (4, 196)
    const int nBL = BB * LL;                  // 6272

    gemm_pre_kernel<false><<<ggrid, 256>>>(xs, ws + 0*nW, bq, Y);
    ln_lif_kernel<<<nBL, 256>>>(Y, gq, beq, 1.0f, qb, nullptr);
    gemm_pre_kernel<false><<<ggrid, 256>>>(xs, ws + 3*nW, bk, Y);
    ln_lif_kernel<<<nBL, 256>>>(Y, gk, bek, 1.0f, kb, nullptr);
    gemm_pre_kernel<false><<<ggrid, 256>>>(xs, ws + 6*nW, bv, Y);
    ln_lif_kernel<<<nBL, 256>>>(Y, gv, bev, 1.0f, vb, nullptr);

    attn_kernel<<<TT * BB * HH, 256>>>(qb, kb, vb, Y);
    lif_attn_kernel<<<(BB * LL * DD + 255) / 256, 256>>>(Y, s2b);

    gemm_pre_kernel<true><<<ggrid, 256>>>(s2b, ws + 9*nW, bl_, Y);
    ln_lif_kernel<<<nBL, 256>>>(Y, gl, bel, 1.0f, nullptr, out);
}

// round 6
// speedup vs baseline: 1.5850x; 1.4003x over previous
#include <cuda_runtime.h>
#include <cuda_bf16.h>
#include <cstdint>
#include <math.h>

// Shapes (fixed)
#define BB 32
#define TT 4
#define LL 196
#define DD 512
#define HH 8
#define ROWS (BB*TT*LL)          // 25088

// Scratch (device globals)
__device__ float g_Y[(size_t)ROWS * DD];
__device__ __nv_bfloat16 g_xs[3 * (size_t)ROWS * DD];   // x split planes
__device__ __nv_bfloat16 g_ws[12 * (size_t)DD * DD];    // 4 weights x 3 planes
__device__ __nv_bfloat16 g_s2b[(size_t)ROWS * DD];      // attn-LIF spikes (bf16 exact)
__device__ unsigned long long g_qb[TT*BB*HH*LL];
__device__ unsigned long long g_kb[TT*BB*HH*LL];
__device__ unsigned long long g_vb[TT*BB*HH*LL];

// ---------------------------------------------------------------------------
// split helpers
// ---------------------------------------------------------------------------
__device__ __forceinline__ void split3(float f, float& s0, float& s1, float& s2) {
    s0 = __bfloat162float(__float2bfloat16_rn(f));
    float r1 = f - s0;
    s1 = __bfloat162float(__float2bfloat16_rn(r1));
    s2 = r1 - s1;
}

__global__ void __launch_bounds__(256) split3_kernel(
    const float* __restrict__ X, __nv_bfloat16* __restrict__ P0,
    __nv_bfloat16* __restrict__ P1, __nv_bfloat16* __restrict__ P2, size_t n)
{
    const size_t idx = ((size_t)blockIdx.x * 256 + threadIdx.x) * 4;
    if (idx >= n) return;
    float4 v = *(const float4*)(X + idx);
    float a0,a1,a2,b0,b1,b2,c0,c1,c2,d0,d1,d2;
    split3(v.x, a0,a1,a2); split3(v.y, b0,b1,b2);
    split3(v.z, c0,c1,c2); split3(v.w, d0,d1,d2);
    *(__nv_bfloat162*)(P0 + idx)     = __nv_bfloat162(__float2bfloat16_rn(a0), __float2bfloat16_rn(b0));
    *(__nv_bfloat162*)(P0 + idx + 2) = __nv_bfloat162(__float2bfloat16_rn(c0), __float2bfloat16_rn(d0));
    *(__nv_bfloat162*)(P1 + idx)     = __nv_bfloat162(__float2bfloat16_rn(a1), __float2bfloat16_rn(b1));
    *(__nv_bfloat162*)(P1 + idx + 2) = __nv_bfloat162(__float2bfloat16_rn(c1), __float2bfloat16_rn(d1));
    *(__nv_bfloat162*)(P2 + idx)     = __nv_bfloat162(__float2bfloat16_rn(a2), __float2bfloat16_rn(b2));
    *(__nv_bfloat162*)(P2 + idx + 2) = __nv_bfloat162(__float2bfloat16_rn(c2), __float2bfloat16_rn(d2));
}

// ---------------------------------------------------------------------------
// bf16x3 GEMM on pre-split planes (R4 version, known passing): C = A@W^T + b
// ---------------------------------------------------------------------------
#define PLANE 1024

__device__ __forceinline__ void mma_bf16(float* c, const uint32_t* a, const uint32_t* b) {
    asm volatile(
        "mma.sync.aligned.m16n8k16.row.col.f32.bf16.bf16.f32 "
        "{%0,%1,%2,%3}, {%4,%5,%6,%7}, {%8,%9}, {%0,%1,%2,%3};\n"
        : "+f"(c[0]), "+f"(c[1]), "+f"(c[2]), "+f"(c[3])
        : "r"(a[0]), "r"(a[1]), "r"(a[2]), "r"(a[3]), "r"(b[0]), "r"(b[1]));
}

template <bool EXACT_A>
__global__ void __launch_bounds__(256) gemm_pre_kernel(
    const __nv_bfloat16* __restrict__ Ap, const __nv_bfloat16* __restrict__ Bp,
    const float* __restrict__ bias, float* __restrict__ C)
{
    constexpr int APL = EXACT_A ? 1 : 3;
    __shared__ uint32_t sA[2][APL * PLANE];
    __shared__ uint32_t sB[2][3 * PLANE];

    const int tid = threadIdx.x;
    const int bn = blockIdx.x * 128, bm = blockIdx.y * 128;
    const int w = tid >> 5, lane = tid & 31;
    const int wm = (w & 1) * 64, wn = (w >> 1) * 32;
    const int g = lane >> 2, tg = lane & 3;

    const int lrow = tid >> 1;
    const int kh = tid & 1;

    float acc[4][4][4];
#pragma unroll
    for (int mi = 0; mi < 4; mi++)
#pragma unroll
        for (int ni = 0; ni < 4; ni++)
#pragma unroll
            for (int r = 0; r < 4; r++) acc[mi][ni][r] = 0.f;

    uint32_t sAa = (uint32_t)__cvta_generic_to_shared(&sA[0][0]);
    uint32_t sBa = (uint32_t)__cvta_generic_to_shared(&sB[0][0]);
    const int dstoff = (kh * 512 + lrow * 4) * 4;

    auto stage_load = [&](int buf, int k0) {
        const uint32_t aBase = sAa + buf * (APL * PLANE * 4) + dstoff;
        const uint32_t bBase = sBa + buf * (3 * PLANE * 4) + dstoff;
#pragma unroll
        for (int p = 0; p < APL; p++) {
            const __nv_bfloat16* src = Ap + (size_t)p * ((size_t)ROWS * DD)
                                          + (size_t)(bm + lrow) * DD + k0 + kh * 8;
            asm volatile("cp.async.cg.shared.global [%0], [%1], 16;\n"
                         :: "r"(aBase + p * PLANE * 4), "l"(src));
        }
#pragma unroll
        for (int p = 0; p < 3; p++) {
            const __nv_bfloat16* src = Bp + (size_t)p * ((size_t)DD * DD)
                                          + (size_t)(bn + lrow) * DD + k0 + kh * 8;
            asm volatile("cp.async.cg.shared.global [%0], [%1], 16;\n"
                         :: "r"(bBase + p * PLANE * 4), "l"(src));
        }
        asm volatile("cp.async.commit_group;\n");
    };

    stage_load(0, 0);

    for (int s = 0; s < DD / 16; s++) {
        const int cur = s & 1;
        if (s + 1 < DD / 16) {
            stage_load(cur ^ 1, (s + 1) * 16);
            asm volatile("cp.async.wait_group 1;\n");
        } else {
            asm volatile("cp.async.wait_group 0;\n");
        }
        __syncthreads();

        uint32_t bf[3][4][2];
#pragma unroll
        for (int p = 0; p < 3; p++)
#pragma unroll
            for (int ni = 0; ni < 4; ni++) {
                const int c0 = wn + ni * 8 + g;
                bf[p][ni][0] = sB[cur][p * PLANE + c0 * 4 + tg];
                bf[p][ni][1] = sB[cur][p * PLANE + 512 + c0 * 4 + tg];
            }
#pragma unroll
        for (int mi = 0; mi < 4; mi++) {
            const int r0 = wm + mi * 16 + g;
            uint32_t af[APL][4];
#pragma unroll
            for (int p = 0; p < APL; p++) {
                af[p][0] = sA[cur][p * PLANE + r0 * 4 + tg];
                af[p][1] = sA[cur][p * PLANE + (r0 + 8) * 4 + tg];
                af[p][2] = sA[cur][p * PLANE + 512 + r0 * 4 + tg];
                af[p][3] = sA[cur][p * PLANE + 512 + (r0 + 8) * 4 + tg];
            }
#pragma unroll
            for (int ni = 0; ni < 4; ni++) {
                mma_bf16(acc[mi][ni], af[0], bf[0][ni]);
                mma_bf16(acc[mi][ni], af[0], bf[1][ni]);
                mma_bf16(acc[mi][ni], af[0], bf[2][ni]);
                if (!EXACT_A) {
                    mma_bf16(acc[mi][ni], af[1], bf[0][ni]);
                    mma_bf16(acc[mi][ni], af[1], bf[1][ni]);
                    mma_bf16(acc[mi][ni], af[2], bf[0][ni]);
                }
            }
        }
        __syncthreads();
    }

#pragma unroll
    for (int mi = 0; mi < 4; mi++) {
        const int row = bm + wm + mi * 16 + g;
#pragma unroll
        for (int ni = 0; ni < 4; ni++) {
            const int col = bn + wn + ni * 8 + tg * 2;
            const float b0 = bias[col], b1 = bias[col + 1];
            *(float2*)(C + (size_t)row * DD + col) =
                make_float2(acc[mi][ni][0] + b0, acc[mi][ni][1] + b1);
            *(float2*)(C + (size_t)(row + 8) * DD + col) =
                make_float2(acc[mi][ni][2] + b0, acc[mi][ni][3] + b1);
        }
    }
}

// ---------------------------------------------------------------------------
// Fused LayerNorm + LIF scan over T + spike emission (unchanged; order is
// load-bearing for spike thresholds).
// ---------------------------------------------------------------------------
__global__ void __launch_bounds__(256) ln_lif_kernel(
    const float* __restrict__ Y, const float* __restrict__ g,
    const float* __restrict__ be, float thr,
    unsigned long long* __restrict__ bits, float* __restrict__ outf)
{
    const int bl = blockIdx.x;
    const int b = bl / LL, l = bl % LL;
    const int tid = threadIdx.x, w = tid >> 5, lane = tid & 31;
    const int cA = w * 64 + lane, cB = cA + 32;
    __shared__ float red[8];
    const float gA = g[cA], gB = g[cB], beA = be[cA], beB = be[cB];
    float vA = 0.f, vB = 0.f;

    for (int t = 0; t < TT; t++) {
        const size_t roff = ((size_t)((b * TT + t) * LL + l)) * DD;
        const float yA = Y[roff + cA], yB = Y[roff + cB];

        float s = yA + yB;
#pragma unroll
        for (int o = 16; o; o >>= 1) s += __shfl_xor_sync(0xffffffffu, s, o);
        if (lane == 0) red[w] = s;
        __syncthreads();
        float S = 0.f;
#pragma unroll
        for (int i = 0; i < 8; i++) S += red[i];
        const float mean = S * (1.f / 512.f);
        __syncthreads();

        const float dA = yA - mean, dB = yB - mean;
        float q = dA * dA + dB * dB;
#pragma unroll
        for (int o = 16; o; o >>= 1) q += __shfl_xor_sync(0xffffffffu, q, o);
        if (lane == 0) red[w] = q;
        __syncthreads();
        float Q = 0.f;
#pragma unroll
        for (int i = 0; i < 8; i++) Q += red[i];
        __syncthreads();
        const float var = Q * (1.f / 512.f);
        const float rstd = (float)(1.0 / sqrt((double)var + 1e-5));

        const float nA = dA * rstd * gA + beA;
        const float nB = dB * rstd * gB + beB;

        vA = (vA + nA) * 0.5f;
        vB = (vB + nB) * 0.5f;
        const bool sA = (vA >= thr), sB = (vB >= thr);
        if (sA) vA = 0.f;
        if (sB) vB = 0.f;

        if (bits) {
            unsigned mA = __ballot_sync(0xffffffffu, sA);
            unsigned mB = __ballot_sync(0xffffffffu, sB);
            if (lane == 0)
                bits[((size_t)(t * BB + b) * HH + w) * LL + l] =
                    (unsigned long long)mA | ((unsigned long long)mB << 32);
        } else {
            outf[roff + cA] = sA ? 1.f : 0.f;
            outf[roff + cB] = sB ? 1.f : 0.f;
        }
    }
}

// ---------------------------------------------------------------------------
// Reassociated binary attention: O = Q @ (K^T @ V) * 0.25 (exact integers).
// One block per (t,b,h).
//  Phase 1: column bitsets Kc[c], Vc[c] (196 j-bits in 7 u32) via ballot.
//  Phase 2: M[c][c'] = sum_j k_jc v_jc' = popcounts; packed u8 4-c per u32.
//  Phase 3: Q rows as u8 bytes (4 c per u32).
//  Phase 4: O[l][c'] = sum_c q_lc M[c][c'] via dp4a (M cols in regs).
// ---------------------------------------------------------------------------
__global__ void __launch_bounds__(256) attn_kernel(
    const unsigned long long* __restrict__ qb,
    const unsigned long long* __restrict__ kb,
    const unsigned long long* __restrict__ vb,
    float* __restrict__ O)
{
    __shared__ unsigned long long qs[LL], ks[LL], vs[LL];
    __shared__ uint32_t sKc[64 * 9], sVc[64 * 9];   // [c][jchunk], pitch 9
    __shared__ uint32_t Mw[64 * 17];                // [c'][i], pitch 17, u8x4 over c
    __shared__ uint32_t Qw[LL * 16];                // [l][i], u8x4 over c

    const int blk = blockIdx.x;            // t*256 + b*8 + h
    const int t = blk >> 8;
    const int b = (blk >> 3) & 31;
    const int h = blk & 7;
    const size_t base = ((size_t)(t * BB + b) * HH + h) * LL;
    const int tid = threadIdx.x, w = tid >> 5, lane = tid & 31;

    if (tid < LL) {
        qs[tid] = qb[base + tid];
        ks[tid] = kb[base + tid];
        vs[tid] = vb[base + tid];
    }
    __syncthreads();

    // Phase 1: bitset transpose via ballot. Warp w handles j-chunk w (0..6).
    if (w < 7) {
        const int j = w * 32 + lane;
        const unsigned long long kv = (j < LL) ? ks[j] : 0ull;
        const unsigned long long vv = (j < LL) ? vs[j] : 0ull;
#pragma unroll
        for (int c = 0; c < 64; c++) {
            unsigned mk = __ballot_sync(0xffffffffu, (unsigned)((kv >> c) & 1ull));
            unsigned mv = __ballot_sync(0xffffffffu, (unsigned)((vv >> c) & 1ull));
            if (lane == 0) { sKc[c * 9 + w] = mk; sVc[c * 9 + w] = mv; }
        }
    }
    __syncthreads();

    // Phase 2: M build. Thread -> c' = tid&63, words i = (tid>>6)*4 .. +3.
    {
        const int cq = tid & 63;
        const int ib = (tid >> 6) * 4;
        uint32_t vc[7];
#pragma unroll
        for (int u = 0; u < 7; u++) vc[u] = sVc[cq * 9 + u];
#pragma unroll
        for (int wd = 0; wd < 4; wd++) {
            const int i = ib + wd;
            uint32_t word = 0;
#pragma unroll
            for (int r = 0; r < 4; r++) {
                const int c = 4 * i + r;
                int s = 0;
#pragma unroll
                for (int u = 0; u < 7; u++) s += __popc(sKc[c * 9 + u] & vc[u]);
                word |= (uint32_t)s << (8 * r);
            }
            Mw[cq * 17 + i] = word;
        }
    }
    // Phase 3: Q bytes. word l,i: bytes = bits 4i..4i+3 of qs[l].
    for (int idx = tid; idx < LL * 16; idx += 256) {
        const int l = idx >> 4, i = idx & 15;
        const uint32_t nib = (uint32_t)(qs[l] >> (4 * i)) & 0xFu;
        Qw[idx] = (nib * 0x00204081u) & 0x01010101u;
    }
    __syncthreads();

    // Phase 4: O rows. Lane owns c' = lane and lane+32; M columns in regs.
    uint32_t MA[16], MB[16];
#pragma unroll
    for (int i = 0; i < 16; i++) {
        MA[i] = Mw[lane * 17 + i];
        MB[i] = Mw[(lane + 32) * 17 + i];
    }
    const int cb = h * 64 + lane;
    for (int l = w; l < LL; l += 8) {
        uint32_t acc0 = 0, acc1 = 0;
        const uint32_t* qrow = &Qw[l * 16];
#pragma unroll
        for (int i4 = 0; i4 < 16; i4 += 4) {
            uint4 qv = *(const uint4*)(qrow + i4);
            acc0 = __dp4a(qv.x, MA[i4 + 0], acc0);
            acc1 = __dp4a(qv.x, MB[i4 + 0], acc1);
            acc0 = __dp4a(qv.y, MA[i4 + 1], acc0);
            acc1 = __dp4a(qv.y, MB[i4 + 1], acc1);
            acc0 = __dp4a(qv.z, MA[i4 + 2], acc0);
            acc1 = __dp4a(qv.z, MB[i4 + 2], acc1);
            acc0 = __dp4a(qv.w, MA[i4 + 3], acc0);
            acc1 = __dp4a(qv.w, MB[i4 + 3], acc1);
        }
        const size_t r0 = ((size_t)((b * TT + t) * LL + l)) * DD;
        O[r0 + cb]      = (float)(int)acc0 * 0.25f;
        O[r0 + cb + 32] = (float)(int)acc1 * 0.25f;
    }
}

// ---------------------------------------------------------------------------
// LIF (thr = 0.5) on attention output. Writes bf16 0/1 spikes (exact).
// ---------------------------------------------------------------------------
__global__ void __launch_bounds__(256) lif_attn_kernel(
    const float* __restrict__ O, __nv_bfloat16* __restrict__ S2)
{
    const int idx = blockIdx.x * 256 + threadIdx.x;
    if (idx >= BB * LL * DD) return;
    const int c = idx & 511;
    const int bl = idx >> 9;
    const int b = bl / LL, l = bl % LL;
    float v = 0.f;
#pragma unroll
    for (int t = 0; t < TT; t++) {
        const size_t off = ((size_t)((b * TT + t) * LL + l)) * DD + c;
        const float x = O[off];
        v = (v + x) * 0.5f;
        const bool s = (v >= 0.5f);
        S2[off] = s ? __float2bfloat16(1.f) : __float2bfloat16(0.f);
        if (s) v = 0.f;
    }
}

// ---------------------------------------------------------------------------
extern "C" void kernel_launch(void* const* d_in, const int* in_sizes, int n_in,
                              void* d_out, int out_size)
{
    const float* x   = (const float*)d_in[0];
    const float* Wq  = (const float*)d_in[1];
    const float* bq  = (const float*)d_in[2];
    const float* gq  = (const float*)d_in[3];
    const float* beq = (const float*)d_in[4];
    const float* Wk  = (const float*)d_in[5];
    const float* bk  = (const float*)d_in[6];
    const float* gk  = (const float*)d_in[7];
    const float* bek = (const float*)d_in[8];
    const float* Wv  = (const float*)d_in[9];
    const float* bv  = (const float*)d_in[10];
    const float* gv  = (const float*)d_in[11];
    const float* bev = (const float*)d_in[12];
    const float* Wl  = (const float*)d_in[13];
    const float* bl_ = (const float*)d_in[14];
    const float* gl  = (const float*)d_in[15];
    const float* bel = (const float*)d_in[16];
    float* out = (float*)d_out;

    float* Y;
    __nv_bfloat16 *xs, *ws, *s2b;
    unsigned long long *qb, *kb, *vb;
    cudaGetSymbolAddress((void**)&Y,   g_Y);
    cudaGetSymbolAddress((void**)&xs,  g_xs);
    cudaGetSymbolAddress((void**)&ws,  g_ws);
    cudaGetSymbolAddress((void**)&s2b, g_s2b);
    cudaGetSymbolAddress((void**)&qb,  g_qb);
    cudaGetSymbolAddress((void**)&kb,  g_kb);
    cudaGetSymbolAddress((void**)&vb,  g_vb);

    const size_t nX = (size_t)ROWS * DD;
    const size_t nW = (size_t)DD * DD;

    split3_kernel<<<(unsigned)(nX / 1024), 256>>>(x,  xs, xs + nX, xs + 2 * nX, nX);
    split3_kernel<<<(unsigned)(nW / 1024), 256>>>(Wq, ws + 0*nW, ws + 1*nW, ws + 2*nW, nW);
    split3_kernel<<<(unsigned)(nW / 1024), 256>>>(Wk, ws + 3*nW, ws + 4*nW, ws + 5*nW, nW);
    split3_kernel<<<(unsigned)(nW / 1024), 256>>>(Wv, ws + 6*nW, ws + 7*nW, ws + 8*nW, nW);
    split3_kernel<<<(unsigned)(nW / 1024), 256>>>(Wl, ws + 9*nW, ws + 10*nW, ws + 11*nW, nW);

    const dim3 ggrid(DD / 128, ROWS / 128);   // (4, 196)
    const int nBL = BB * LL;                  // 6272

    gemm_pre_kernel<false><<<ggrid, 256>>>(xs, ws + 0*nW, bq, Y);
    ln_lif_kernel<<<nBL, 256>>>(Y, gq, beq, 1.0f, qb, nullptr);
    gemm_pre_kernel<false><<<ggrid, 256>>>(xs, ws + 3*nW, bk, Y);
    ln_lif_kernel<<<nBL, 256>>>(Y, gk, bek, 1.0f, kb, nullptr);
    gemm_pre_kernel<false><<<ggrid, 256>>>(xs, ws + 6*nW, bv, Y);
    ln_lif_kernel<<<nBL, 256>>>(Y, gv, bev, 1.0f, vb, nullptr);

    attn_kernel<<<TT * BB * HH, 256>>>(qb, kb, vb, Y);
    lif_attn_kernel<<<(BB * LL * DD + 255) / 256, 256>>>(Y, s2b);

    gemm_pre_kernel<true><<<ggrid, 256>>>(s2b, ws + 9*nW, bl_, Y);
    ln_lif_kernel<<<nBL, 256>>>(Y, gl, bel, 1.0f, nullptr, out);
}

// round 7
// speedup vs baseline: 1.6086x; 1.0149x over previous
#include <cuda_runtime.h>
#include <cuda_bf16.h>
#include <cstdint>
#include <math.h>

// Shapes (fixed)
#define BB 32
#define TT 4
#define LL 196
#define DD 512
#define HH 8
#define ROWS (BB*TT*LL)          // 25088

// Scratch (device globals)
__device__ float g_Y[(size_t)ROWS * DD];
__device__ __nv_bfloat16 g_xs[3 * (size_t)ROWS * DD];   // x split planes
__device__ __nv_bfloat16 g_ws[12 * (size_t)DD * DD];    // 4 weights x 3 planes
__device__ __nv_bfloat16 g_s2b[(size_t)ROWS * DD];      // attn-LIF spikes (bf16 exact)
__device__ unsigned long long g_qb[TT*BB*HH*LL];
__device__ unsigned long long g_kb[TT*BB*HH*LL];
__device__ unsigned long long g_vb[TT*BB*HH*LL];

// ---------------------------------------------------------------------------
// split helpers
// ---------------------------------------------------------------------------
__device__ __forceinline__ void split3(float f, float& s0, float& s1, float& s2) {
    s0 = __bfloat162float(__float2bfloat16_rn(f));
    float r1 = f - s0;
    s1 = __bfloat162float(__float2bfloat16_rn(r1));
    s2 = r1 - s1;
}

__global__ void __launch_bounds__(256) split3_kernel(
    const float* __restrict__ X, __nv_bfloat16* __restrict__ P0,
    __nv_bfloat16* __restrict__ P1, __nv_bfloat16* __restrict__ P2, size_t n)
{
    const size_t idx = ((size_t)blockIdx.x * 256 + threadIdx.x) * 4;
    if (idx >= n) return;
    float4 v = *(const float4*)(X + idx);
    float a0,a1,a2,b0,b1,b2,c0,c1,c2,d0,d1,d2;
    split3(v.x, a0,a1,a2); split3(v.y, b0,b1,b2);
    split3(v.z, c0,c1,c2); split3(v.w, d0,d1,d2);
    *(__nv_bfloat162*)(P0 + idx)     = __nv_bfloat162(__float2bfloat16_rn(a0), __float2bfloat16_rn(b0));
    *(__nv_bfloat162*)(P0 + idx + 2) = __nv_bfloat162(__float2bfloat16_rn(c0), __float2bfloat16_rn(d0));
    *(__nv_bfloat162*)(P1 + idx)     = __nv_bfloat162(__float2bfloat16_rn(a1), __float2bfloat16_rn(b1));
    *(__nv_bfloat162*)(P1 + idx + 2) = __nv_bfloat162(__float2bfloat16_rn(c1), __float2bfloat16_rn(d1));
    *(__nv_bfloat162*)(P2 + idx)     = __nv_bfloat162(__float2bfloat16_rn(a2), __float2bfloat16_rn(b2));
    *(__nv_bfloat162*)(P2 + idx + 2) = __nv_bfloat162(__float2bfloat16_rn(c2), __float2bfloat16_rn(d2));
}

// ---------------------------------------------------------------------------
// bf16x3 GEMM on pre-split planes (unchanged, known passing)
// ---------------------------------------------------------------------------
#define PLANE 1024

__device__ __forceinline__ void mma_bf16(float* c, const uint32_t* a, const uint32_t* b) {
    asm volatile(
        "mma.sync.aligned.m16n8k16.row.col.f32.bf16.bf16.f32 "
        "{%0,%1,%2,%3}, {%4,%5,%6,%7}, {%8,%9}, {%0,%1,%2,%3};\n"
        : "+f"(c[0]), "+f"(c[1]), "+f"(c[2]), "+f"(c[3])
        : "r"(a[0]), "r"(a[1]), "r"(a[2]), "r"(a[3]), "r"(b[0]), "r"(b[1]));
}

template <bool EXACT_A>
__global__ void __launch_bounds__(256) gemm_pre_kernel(
    const __nv_bfloat16* __restrict__ Ap, const __nv_bfloat16* __restrict__ Bp,
    const float* __restrict__ bias, float* __restrict__ C)
{
    constexpr int APL = EXACT_A ? 1 : 3;
    __shared__ uint32_t sA[2][APL * PLANE];
    __shared__ uint32_t sB[2][3 * PLANE];

    const int tid = threadIdx.x;
    const int bn = blockIdx.x * 128, bm = blockIdx.y * 128;
    const int w = tid >> 5, lane = tid & 31;
    const int wm = (w & 1) * 64, wn = (w >> 1) * 32;
    const int g = lane >> 2, tg = lane & 3;

    const int lrow = tid >> 1;
    const int kh = tid & 1;

    float acc[4][4][4];
#pragma unroll
    for (int mi = 0; mi < 4; mi++)
#pragma unroll
        for (int ni = 0; ni < 4; ni++)
#pragma unroll
            for (int r = 0; r < 4; r++) acc[mi][ni][r] = 0.f;

    uint32_t sAa = (uint32_t)__cvta_generic_to_shared(&sA[0][0]);
    uint32_t sBa = (uint32_t)__cvta_generic_to_shared(&sB[0][0]);
    const int dstoff = (kh * 512 + lrow * 4) * 4;

    auto stage_load = [&](int buf, int k0) {
        const uint32_t aBase = sAa + buf * (APL * PLANE * 4) + dstoff;
        const uint32_t bBase = sBa + buf * (3 * PLANE * 4) + dstoff;
#pragma unroll
        for (int p = 0; p < APL; p++) {
            const __nv_bfloat16* src = Ap + (size_t)p * ((size_t)ROWS * DD)
                                          + (size_t)(bm + lrow) * DD + k0 + kh * 8;
            asm volatile("cp.async.cg.shared.global [%0], [%1], 16;\n"
                         :: "r"(aBase + p * PLANE * 4), "l"(src));
        }
#pragma unroll
        for (int p = 0; p < 3; p++) {
            const __nv_bfloat16* src = Bp + (size_t)p * ((size_t)DD * DD)
                                          + (size_t)(bn + lrow) * DD + k0 + kh * 8;
            asm volatile("cp.async.cg.shared.global [%0], [%1], 16;\n"
                         :: "r"(bBase + p * PLANE * 4), "l"(src));
        }
        asm volatile("cp.async.commit_group;\n");
    };

    stage_load(0, 0);

    for (int s = 0; s < DD / 16; s++) {
        const int cur = s & 1;
        if (s + 1 < DD / 16) {
            stage_load(cur ^ 1, (s + 1) * 16);
            asm volatile("cp.async.wait_group 1;\n");
        } else {
            asm volatile("cp.async.wait_group 0;\n");
        }
        __syncthreads();

        uint32_t bf[3][4][2];
#pragma unroll
        for (int p = 0; p < 3; p++)
#pragma unroll
            for (int ni = 0; ni < 4; ni++) {
                const int c0 = wn + ni * 8 + g;
                bf[p][ni][0] = sB[cur][p * PLANE + c0 * 4 + tg];
                bf[p][ni][1] = sB[cur][p * PLANE + 512 + c0 * 4 + tg];
            }
#pragma unroll
        for (int mi = 0; mi < 4; mi++) {
            const int r0 = wm + mi * 16 + g;
            uint32_t af[APL][4];
#pragma unroll
            for (int p = 0; p < APL; p++) {
                af[p][0] = sA[cur][p * PLANE + r0 * 4 + tg];
                af[p][1] = sA[cur][p * PLANE + (r0 + 8) * 4 + tg];
                af[p][2] = sA[cur][p * PLANE + 512 + r0 * 4 + tg];
                af[p][3] = sA[cur][p * PLANE + 512 + (r0 + 8) * 4 + tg];
            }
#pragma unroll
            for (int ni = 0; ni < 4; ni++) {
                mma_bf16(acc[mi][ni], af[0], bf[0][ni]);
                mma_bf16(acc[mi][ni], af[0], bf[1][ni]);
                mma_bf16(acc[mi][ni], af[0], bf[2][ni]);
                if (!EXACT_A) {
                    mma_bf16(acc[mi][ni], af[1], bf[0][ni]);
                    mma_bf16(acc[mi][ni], af[1], bf[1][ni]);
                    mma_bf16(acc[mi][ni], af[2], bf[0][ni]);
                }
            }
        }
        __syncthreads();
    }

#pragma unroll
    for (int mi = 0; mi < 4; mi++) {
        const int row = bm + wm + mi * 16 + g;
#pragma unroll
        for (int ni = 0; ni < 4; ni++) {
            const int col = bn + wn + ni * 8 + tg * 2;
            const float b0 = bias[col], b1 = bias[col + 1];
            *(float2*)(C + (size_t)row * DD + col) =
                make_float2(acc[mi][ni][0] + b0, acc[mi][ni][1] + b1);
            *(float2*)(C + (size_t)(row + 8) * DD + col) =
                make_float2(acc[mi][ni][2] + b0, acc[mi][ni][3] + b1);
        }
    }
}

// ---------------------------------------------------------------------------
// Barrier-free LayerNorm + LIF. One WARP per (b,l) row; lane holds channels
// i*64+lane and i*64+32+lane for i=0..7 (i plays old warp role w).
// Arithmetic is bit-identical to the previous block version: same per-lane
// sums, same shuffle-tree order per head, same 0..7 fold order.
// ---------------------------------------------------------------------------
__global__ void __launch_bounds__(256) ln_lif_kernel(
    const float* __restrict__ Y, const float* __restrict__ g,
    const float* __restrict__ be, float thr,
    unsigned long long* __restrict__ bits, float* __restrict__ outf)
{
    const int wg = blockIdx.x * 8 + (threadIdx.x >> 5);
    if (wg >= BB * LL) return;
    const int b = wg / LL, l = wg % LL;
    const int lane = threadIdx.x & 31;

    float gA[8], gB[8], beA[8], beB[8], vA[8], vB[8];
#pragma unroll
    for (int i = 0; i < 8; i++) {
        gA[i]  = g[i * 64 + lane];       gB[i]  = g[i * 64 + 32 + lane];
        beA[i] = be[i * 64 + lane];      beB[i] = be[i * 64 + 32 + lane];
        vA[i] = 0.f; vB[i] = 0.f;
    }

    for (int t = 0; t < TT; t++) {
        const size_t roff = ((size_t)((b * TT + t) * LL + l)) * DD;
        float yA[8], yB[8], s[8];
#pragma unroll
        for (int i = 0; i < 8; i++) {
            yA[i] = Y[roff + i * 64 + lane];
            yB[i] = Y[roff + i * 64 + 32 + lane];
            s[i] = yA[i] + yB[i];
        }
#pragma unroll
        for (int o = 16; o; o >>= 1)
#pragma unroll
            for (int i = 0; i < 8; i++) s[i] += __shfl_xor_sync(0xffffffffu, s[i], o);
        float S = 0.f;
#pragma unroll
        for (int i = 0; i < 8; i++) S += s[i];
        const float mean = S * (1.f / 512.f);

        float dA[8], dB[8], q[8];
#pragma unroll
        for (int i = 0; i < 8; i++) {
            dA[i] = yA[i] - mean; dB[i] = yB[i] - mean;
            q[i] = dA[i] * dA[i] + dB[i] * dB[i];
        }
#pragma unroll
        for (int o = 16; o; o >>= 1)
#pragma unroll
            for (int i = 0; i < 8; i++) q[i] += __shfl_xor_sync(0xffffffffu, q[i], o);
        float Q = 0.f;
#pragma unroll
        for (int i = 0; i < 8; i++) Q += q[i];
        const float var = Q * (1.f / 512.f);
        const float rstd = (float)(1.0 / sqrt((double)var + 1e-5));

        unsigned long long rowbits[8];
#pragma unroll
        for (int i = 0; i < 8; i++) {
            const float nA = dA[i] * rstd * gA[i] + beA[i];
            const float nB = dB[i] * rstd * gB[i] + beB[i];
            vA[i] = (vA[i] + nA) * 0.5f;
            vB[i] = (vB[i] + nB) * 0.5f;
            const bool sA = (vA[i] >= thr), sB = (vB[i] >= thr);
            if (sA) vA[i] = 0.f;
            if (sB) vB[i] = 0.f;
            if (bits) {
                unsigned mA = __ballot_sync(0xffffffffu, sA);
                unsigned mB = __ballot_sync(0xffffffffu, sB);
                rowbits[i] = (unsigned long long)mA | ((unsigned long long)mB << 32);
            } else {
                outf[roff + i * 64 + lane]      = sA ? 1.f : 0.f;
                outf[roff + i * 64 + 32 + lane] = sB ? 1.f : 0.f;
            }
        }
        if (bits && lane == 0) {
#pragma unroll
            for (int i = 0; i < 8; i++)
                bits[((size_t)(t * BB + b) * HH + i) * LL + l] = rowbits[i];
        }
    }
}

// ---------------------------------------------------------------------------
// Fused attention + attn-LIF: O = Q @ (K^T V) * 0.25, then LIF(thr=0.5) over
// t, emitting bf16 spikes. Block = (b, h, quarter); warp owns rows
// l = l0 + w + 8r; LIF membrane state lives in registers across the t loop.
// All integer/dyadic math -> exact.
// ---------------------------------------------------------------------------
#define QROWS 49

__global__ void __launch_bounds__(256) attn_lif_kernel(
    const unsigned long long* __restrict__ qb,
    const unsigned long long* __restrict__ kb,
    const unsigned long long* __restrict__ vb,
    __nv_bfloat16* __restrict__ S2)
{
    __shared__ unsigned long long qs[LL], ks[LL], vs[LL];
    __shared__ uint32_t sKc[64 * 9], sVc[64 * 9];
    __shared__ uint32_t Mw[64 * 17];
    __shared__ uint32_t Qw[QROWS * 16];

    const int blk = blockIdx.x;              // b*32 + h*4 + s
    const int qr = blk & 3;
    const int h = (blk >> 2) & 7;
    const int b = blk >> 5;
    const int l0 = qr * QROWS;
    const int tid = threadIdx.x, w = tid >> 5, lane = tid & 31;
    const int cb = h * 64 + lane;

    float vSA[7], vSB[7];
#pragma unroll
    for (int r = 0; r < 7; r++) { vSA[r] = 0.f; vSB[r] = 0.f; }

    for (int t = 0; t < TT; t++) {
        const size_t base = ((size_t)(t * BB + b) * HH + h) * LL;
        if (tid < LL) {
            qs[tid] = qb[base + tid];
            ks[tid] = kb[base + tid];
            vs[tid] = vb[base + tid];
        }
        __syncthreads();

        // bitset transpose via ballot: warp w -> j-chunk w (0..6)
        if (w < 7) {
            const int j = w * 32 + lane;
            const unsigned long long kv = (j < LL) ? ks[j] : 0ull;
            const unsigned long long vv = (j < LL) ? vs[j] : 0ull;
#pragma unroll
            for (int c = 0; c < 64; c++) {
                unsigned mk = __ballot_sync(0xffffffffu, (unsigned)((kv >> c) & 1ull));
                unsigned mv = __ballot_sync(0xffffffffu, (unsigned)((vv >> c) & 1ull));
                if (lane == 0) { sKc[c * 9 + w] = mk; sVc[c * 9 + w] = mv; }
            }
        }
        __syncthreads();

        // M[c][c'] build (u8 packed, 4 c per word)
        {
            const int cq = tid & 63;
            const int ib = (tid >> 6) * 4;
            uint32_t vc[7];
#pragma unroll
            for (int u = 0; u < 7; u++) vc[u] = sVc[cq * 9 + u];
#pragma unroll
            for (int wd = 0; wd < 4; wd++) {
                const int i = ib + wd;
                uint32_t word = 0;
#pragma unroll
                for (int r = 0; r < 4; r++) {
                    const int c = 4 * i + r;
                    int s = 0;
#pragma unroll
                    for (int u = 0; u < 7; u++) s += __popc(sKc[c * 9 + u] & vc[u]);
                    word |= (uint32_t)s << (8 * r);
                }
                Mw[cq * 17 + i] = word;
            }
        }
        // Q bytes for our rows
        for (int idx = tid; idx < QROWS * 16; idx += 256) {
            const int l = l0 + (idx >> 4), i = idx & 15;
            const uint32_t nib = (uint32_t)(qs[l] >> (4 * i)) & 0xFu;
            Qw[idx] = (nib * 0x00204081u) & 0x01010101u;
        }
        __syncthreads();

        uint32_t MA[16], MB[16];
#pragma unroll
        for (int i = 0; i < 16; i++) {
            MA[i] = Mw[lane * 17 + i];
            MB[i] = Mw[(lane + 32) * 17 + i];
        }
#pragma unroll
        for (int r = 0; r < 7; r++) {
            const int lr = w + 8 * r;
            if (lr < QROWS) {
                const int l = l0 + lr;
                uint32_t acc0 = 0, acc1 = 0;
                const uint32_t* qrow = &Qw[lr * 16];
#pragma unroll
                for (int i4 = 0; i4 < 16; i4 += 4) {
                    uint4 qv = *(const uint4*)(qrow + i4);
                    acc0 = __dp4a(qv.x, MA[i4 + 0], acc0);
                    acc1 = __dp4a(qv.x, MB[i4 + 0], acc1);
                    acc0 = __dp4a(qv.y, MA[i4 + 1], acc0);
                    acc1 = __dp4a(qv.y, MB[i4 + 1], acc1);
                    acc0 = __dp4a(qv.z, MA[i4 + 2], acc0);
                    acc1 = __dp4a(qv.z, MB[i4 + 2], acc1);
                    acc0 = __dp4a(qv.w, MA[i4 + 3], acc0);
                    acc1 = __dp4a(qv.w, MB[i4 + 3], acc1);
                }
                const float xA = (float)(int)acc0 * 0.25f;
                const float xB = (float)(int)acc1 * 0.25f;
                vSA[r] = (vSA[r] + xA) * 0.5f;
                vSB[r] = (vSB[r] + xB) * 0.5f;
                const bool sA = (vSA[r] >= 0.5f), sB = (vSB[r] >= 0.5f);
                if (sA) vSA[r] = 0.f;
                if (sB) vSB[r] = 0.f;
                const size_t off = ((size_t)((b * TT + t) * LL + l)) * DD;
                S2[off + cb]      = sA ? __float2bfloat16(1.f) : __float2bfloat16(0.f);
                S2[off + cb + 32] = sB ? __float2bfloat16(1.f) : __float2bfloat16(0.f);
            }
        }
        __syncthreads();
    }
}

// ---------------------------------------------------------------------------
extern "C" void kernel_launch(void* const* d_in, const int* in_sizes, int n_in,
                              void* d_out, int out_size)
{
    const float* x   = (const float*)d_in[0];
    const float* Wq  = (const float*)d_in[1];
    const float* bq  = (const float*)d_in[2];
    const float* gq  = (const float*)d_in[3];
    const float* beq = (const float*)d_in[4];
    const float* Wk  = (const float*)d_in[5];
    const float* bk  = (const float*)d_in[6];
    const float* gk  = (const float*)d_in[7];
    const float* bek = (const float*)d_in[8];
    const float* Wv  = (const float*)d_in[9];
    const float* bv  = (const float*)d_in[10];
    const float* gv  = (const float*)d_in[11];
    const float* bev = (const float*)d_in[12];
    const float* Wl  = (const float*)d_in[13];
    const float* bl_ = (const float*)d_in[14];
    const float* gl  = (const float*)d_in[15];
    const float* bel = (const float*)d_in[16];
    float* out = (float*)d_out;

    float* Y;
    __nv_bfloat16 *xs, *ws, *s2b;
    unsigned long long *qb, *kb, *vb;
    cudaGetSymbolAddress((void**)&Y,   g_Y);
    cudaGetSymbolAddress((void**)&xs,  g_xs);
    cudaGetSymbolAddress((void**)&ws,  g_ws);
    cudaGetSymbolAddress((void**)&s2b, g_s2b);
    cudaGetSymbolAddress((void**)&qb,  g_qb);
    cudaGetSymbolAddress((void**)&kb,  g_kb);
    cudaGetSymbolAddress((void**)&vb,  g_vb);

    const size_t nX = (size_t)ROWS * DD;
    const size_t nW = (size_t)DD * DD;

    split3_kernel<<<(unsigned)(nX / 1024), 256>>>(x,  xs, xs + nX, xs + 2 * nX, nX);
    split3_kernel<<<(unsigned)(nW / 1024), 256>>>(Wq, ws + 0*nW, ws + 1*nW, ws + 2*nW, nW);
    split3_kernel<<<(unsigned)(nW / 1024), 256>>>(Wk, ws + 3*nW, ws + 4*nW, ws + 5*nW, nW);
    split3_kernel<<<(unsigned)(nW / 1024), 256>>>(Wv, ws + 6*nW, ws + 7*nW, ws + 8*nW, nW);
    split3_kernel<<<(unsigned)(nW / 1024), 256>>>(Wl, ws + 9*nW, ws + 10*nW, ws + 11*nW, nW);

    const dim3 ggrid(DD / 128, ROWS / 128);   // (4, 196)
    const int nLN = (BB * LL) / 8;            // 784 blocks, 1 warp per row

    gemm_pre_kernel<false><<<ggrid, 256>>>(xs, ws + 0*nW, bq, Y);
    ln_lif_kernel<<<nLN, 256>>>(Y, gq, beq, 1.0f, qb, nullptr);
    gemm_pre_kernel<false><<<ggrid, 256>>>(xs, ws + 3*nW, bk, Y);
    ln_lif_kernel<<<nLN, 256>>>(Y, gk, bek, 1.0f, kb, nullptr);
    gemm_pre_kernel<false><<<ggrid, 256>>>(xs, ws + 6*nW, bv, Y);
    ln_lif_kernel<<<nLN, 256>>>(Y, gv, bev, 1.0f, vb, nullptr);

    attn_lif_kernel<<<BB * HH * 4, 256>>>(qb, kb, vb, s2b);

    gemm_pre_kernel<true><<<ggrid, 256>>>(s2b, ws + 9*nW, bl_, Y);
    ln_lif_kernel<<<nLN, 256>>>(Y, gl, bel, 1.0f, nullptr, out);
}